// round 16
// baseline (speedup 1.0000x reference)
#include <cuda_runtime.h>
#include <cuda_bf16.h>
#include <stdint.h>
#include <math.h>

#define BATCH 2
#define SEQ   2048
#define DM    1024
#define NH    16
#define DH    64
#define MELEMS (BATCH*SEQ*DM)   // 4194304
#define WELEMS (DM*DM)          // 1048576

#define QSCALE 0.18033688f      // 0.125 * log2(e)
#define MASKED (-1.44269504e9f) // -1e9 * log2(e)

// ---- split-bf16 scratch (allocation-free rule: __device__ globals) ----
__device__ __nv_bfloat16 g_qin_hi[MELEMS], g_qin_lo[MELEMS];
__device__ __nv_bfloat16 g_kin_hi[MELEMS], g_kin_lo[MELEMS];
__device__ __nv_bfloat16 g_vin_hi[MELEMS], g_vin_lo[MELEMS];
__device__ __nv_bfloat16 g_wq_hi[WELEMS], g_wq_lo[WELEMS];
__device__ __nv_bfloat16 g_wk_hi[WELEMS], g_wk_lo[WELEMS];
__device__ __nv_bfloat16 g_wv_hi[WELEMS], g_wv_lo[WELEMS];
__device__ __nv_bfloat16 g_wo_hi[WELEMS], g_wo_lo[WELEMS];
__device__ __nv_bfloat16 g_Q_hi[MELEMS], g_Q_lo[MELEMS];
__device__ __nv_bfloat16 g_K_hi[MELEMS], g_K_lo[MELEMS];
__device__ __nv_bfloat16 g_V_hi[MELEMS], g_V_lo[MELEMS];
__device__ __nv_bfloat16 g_at_hi[MELEMS], g_at_lo[MELEMS];
// compacted K/V (unmasked keys only)
__device__ __nv_bfloat16 g_Kc_hi[MELEMS], g_Kc_lo[MELEMS];
__device__ __nv_bfloat16 g_Vc_hi[MELEMS], g_Vc_lo[MELEMS];
__device__ int g_idx[BATCH*SEQ];
__device__ int g_nk[BATCH];

// ============================================================================
// Helpers
// ============================================================================
__device__ __forceinline__ uint32_t smem_u32(const void* p) {
    uint32_t a;
    asm("{ .reg .u64 t; cvta.to.shared.u64 t, %1; cvt.u32.u64 %0, t; }"
        : "=r"(a) : "l"(p));
    return a;
}
__device__ __forceinline__ void cp_async16(uint32_t dst, const void* src) {
    asm volatile("cp.async.cg.shared.global [%0], [%1], 16;"
                 :: "r"(dst), "l"(src) : "memory");
}
#define CP_COMMIT() asm volatile("cp.async.commit_group;" ::: "memory")
#define CP_WAIT0()  asm volatile("cp.async.wait_group 0;" ::: "memory")

__device__ __forceinline__ void ldmatrix_x4(uint32_t* r, uint32_t addr) {
    asm volatile("ldmatrix.sync.aligned.m8n8.x4.shared.b16 {%0,%1,%2,%3}, [%4];"
                 : "=r"(r[0]), "=r"(r[1]), "=r"(r[2]), "=r"(r[3]) : "r"(addr));
}
__device__ __forceinline__ void ldmatrix_x4_trans(uint32_t* r, uint32_t addr) {
    asm volatile("ldmatrix.sync.aligned.m8n8.x4.trans.shared.b16 {%0,%1,%2,%3}, [%4];"
                 : "=r"(r[0]), "=r"(r[1]), "=r"(r[2]), "=r"(r[3]) : "r"(addr));
}
__device__ __forceinline__ void mma_bf16(float* d, const uint32_t* a, const uint32_t* b,
                                         const float* c) {
    asm volatile(
        "mma.sync.aligned.m16n8k16.row.col.f32.bf16.bf16.f32 "
        "{%0,%1,%2,%3}, {%4,%5,%6,%7}, {%8,%9}, {%10,%11,%12,%13};"
        : "=f"(d[0]), "=f"(d[1]), "=f"(d[2]), "=f"(d[3])
        : "r"(a[0]), "r"(a[1]), "r"(a[2]), "r"(a[3]),
          "r"(b[0]), "r"(b[1]),
          "f"(c[0]), "f"(c[1]), "f"(c[2]), "f"(c[3]));
}

__device__ __forceinline__ uint32_t cvt_bf16x2(float x, float y) {
    uint32_t r;
    asm("cvt.rn.bf16x2.f32 %0, %1, %2;" : "=r"(r) : "f"(y), "f"(x));
    return r;
}
__device__ __forceinline__ void pack_hilo(float x, float y, uint32_t& hi, uint32_t& lo) {
    hi = cvt_bf16x2(x, y);
    float fx = __uint_as_float(hi << 16);
    float fy = __uint_as_float(hi & 0xffff0000u);
    lo = cvt_bf16x2(x - fx, y - fy);
}

#define TSTRB 144   // 9 * 16B: conflict-free, 16B-aligned rows

// ============================================================================
// Pre-pass: fp32 -> hi/lo bf16 split (region-batched)
// ============================================================================
__global__ void split3_kernel(const float4* s0, const float4* s1, const float4* s2,
                              uint2* h0, uint2* l0, uint2* h1, uint2* l1,
                              uint2* h2, uint2* l2, int n4) {
    int i = blockIdx.x * 256 + threadIdx.x;
    if (i >= n4) return;
    int r = blockIdx.y;
    const float4* s = (r == 0) ? s0 : (r == 1) ? s1 : s2;
    uint2* hd = (r == 0) ? h0 : (r == 1) ? h1 : h2;
    uint2* ld = (r == 0) ? l0 : (r == 1) ? l1 : l2;
    float4 v = s[i];
    uint2 hp, lp;
    pack_hilo(v.x, v.y, hp.x, lp.x);
    pack_hilo(v.z, v.w, hp.y, lp.y);
    hd[i] = hp; ld[i] = lp;
}

__global__ void split4_kernel(const float4* s0, const float4* s1,
                              const float4* s2, const float4* s3,
                              uint2* h0, uint2* l0, uint2* h1, uint2* l1,
                              uint2* h2, uint2* l2, uint2* h3, uint2* l3, int n4) {
    int i = blockIdx.x * 256 + threadIdx.x;
    if (i >= n4) return;
    int r = blockIdx.y;
    const float4* s = (r == 0) ? s0 : (r == 1) ? s1 : (r == 2) ? s2 : s3;
    uint2* hd = (r == 0) ? h0 : (r == 1) ? h1 : (r == 2) ? h2 : h3;
    uint2* ld = (r == 0) ? l0 : (r == 1) ? l1 : (r == 2) ? l2 : l3;
    float4 v = s[i];
    uint2 hp, lp;
    pack_hilo(v.x, v.y, hp.x, lp.x);
    pack_hilo(v.z, v.w, hp.y, lp.y);
    hd[i] = hp; ld[i] = lp;
}

// ============================================================================
// Mask compaction: idx[b][r] = r-th unmasked key position; nk[b] = count.
// ============================================================================
__global__ void mask_compact_idx(const int* __restrict__ mask,
                                 int* __restrict__ idx, int* __restrict__ nk) {
    const int b = blockIdx.x;
    const int lane = threadIdx.x;   // 32 threads
    int base = 0;
    for (int i = 0; i < SEQ; i += 32) {
        int m = mask[b * SEQ + i + lane] != 0;
        unsigned bal = __ballot_sync(0xffffffffu, m);
        int pos = base + __popc(bal & ((1u << lane) - 1u));
        if (m) idx[b * SEQ + pos] = i + lane;
        base += __popc(bal);
    }
    if (lane == 0) nk[b] = base;
}

// Gather K/V hi/lo rows into compacted buffers; zero-fill to 64-row multiple.
__global__ void gather_kv(const uint4* __restrict__ khi, const uint4* __restrict__ klo,
                          const uint4* __restrict__ vhi, const uint4* __restrict__ vlo,
                          uint4* __restrict__ kchi, uint4* __restrict__ kclo,
                          uint4* __restrict__ vchi, uint4* __restrict__ vclo,
                          const int* __restrict__ idx, const int* __restrict__ nk) {
    const int r = blockIdx.x;
    const int b = blockIdx.y;
    const int n = nk[b];
    const int rt = (n + 63) & ~63;
    if (r >= rt) return;
    const int tid = threadIdx.x;     // 128, DM/8 = 128 uint4 per row
    const size_t drow = ((size_t)(b * SEQ + r)) * (DM / 8) + tid;
    if (r < n) {
        const size_t srow = ((size_t)(b * SEQ + idx[b * SEQ + r])) * (DM / 8) + tid;
        kchi[drow] = khi[srow];
        kclo[drow] = klo[srow];
        vchi[drow] = vhi[srow];
        vclo[drow] = vlo[srow];
    } else {
        uint4 z = make_uint4(0, 0, 0, 0);
        kchi[drow] = z; kclo[drow] = z; vchi[drow] = z; vclo[drow] = z;
    }
}

// ============================================================================
// Pre-split GEMM core:  C[M,N] = (A @ W^T + bias) * scale
// 128x128 tile, K-chunk 64, cp.async double buffer, 3-pass split-bf16.
// Pass-major MMA order: chain distance 16 on each accumulator.
// ============================================================================
#define G_STG   73728
#define GEMM_PS_SMEM (2 * G_STG)   // 147456

template<int OUT_SPLIT>
__device__ __forceinline__ void gemm_core(
    char* sm,
    const __nv_bfloat16* __restrict__ Ahi, const __nv_bfloat16* __restrict__ Alo,
    const __nv_bfloat16* __restrict__ Whi, const __nv_bfloat16* __restrict__ Wlo,
    const float* __restrict__ bias,
    float* __restrict__ Cf, __nv_bfloat16* __restrict__ Chi, __nv_bfloat16* __restrict__ Clo,
    float scale, int m0, int n0, int N, int K)
{
    const int tid = threadIdx.x;
    const int wid = tid >> 5;
    const int lane = tid & 31;
    const int wm = wid >> 1;
    const int wn = wid & 1;
    const uint32_t u = smem_u32(sm);

    const __nv_bfloat16* const srcA[2] = {Ahi, Alo};
    const __nv_bfloat16* const srcB[2] = {Whi, Wlo};

    auto issue = [&](int c, int s) {
        const int k0 = c * 64;
        const uint32_t sb = u + s * G_STG;
        #pragma unroll
        for (int half = 0; half < 2; half++)
            #pragma unroll
            for (int j = 0; j < 4; j++) {
                int cc = tid + j * 256;
                int row = cc >> 3, ch = cc & 7;
                cp_async16(sb + half * 18432 + row * TSTRB + ch * 16,
                           srcA[half] + (size_t)(m0 + row) * K + k0 + ch * 8);
                cp_async16(sb + 36864 + half * 18432 + row * TSTRB + ch * 16,
                           srcB[half] + (size_t)(n0 + row) * K + k0 + ch * 8);
            }
    };

    float acc[2][8][4];
    #pragma unroll
    for (int i = 0; i < 2; i++)
        #pragma unroll
        for (int j = 0; j < 8; j++)
            #pragma unroll
            for (int t = 0; t < 4; t++) acc[i][j][t] = 0.f;

    const uint32_t a_row = (uint32_t)(wm * 32 + (lane & 15));
    const uint32_t a_kof = (uint32_t)((lane >> 4) * 8) * 2;
    const uint32_t b_row = (uint32_t)(wn * 64 + (lane & 7) + ((lane >> 4) & 1) * 8);
    const uint32_t b_kof = (uint32_t)(((lane >> 3) & 1) * 8) * 2;

    issue(0, 0); CP_COMMIT();

    const int nchunk = K / 64;
    for (int c = 0; c < nchunk; ++c) {
        const int cur = c & 1;
        CP_WAIT0();
        __syncthreads();
        if (c + 1 < nchunk) { issue(c + 1, cur ^ 1); CP_COMMIT(); }

        const uint32_t sb = u + cur * G_STG;
        #pragma unroll
        for (int ks = 0; ks < 4; ks++) {
            const uint32_t kbyte = (uint32_t)(ks * 16) * 2;
            uint32_t aHi[2][4], aLo[2][4], bHi[4][4], bLo[4][4];
            #pragma unroll
            for (int mi = 0; mi < 2; mi++) {
                uint32_t ar = sb + (a_row + mi * 16) * TSTRB + kbyte + a_kof;
                ldmatrix_x4(aHi[mi], ar);
                ldmatrix_x4(aLo[mi], ar + 18432);
            }
            #pragma unroll
            for (int nt2 = 0; nt2 < 4; nt2++) {
                uint32_t br = sb + 36864 + (b_row + nt2 * 16) * TSTRB + kbyte + b_kof;
                ldmatrix_x4(bHi[nt2], br);
                ldmatrix_x4(bLo[nt2], br + 18432);
            }
            // pass-major: 16 independent MMAs per pass -> chain distance 16
            #pragma unroll
            for (int mi = 0; mi < 2; mi++)
                #pragma unroll
                for (int nt = 0; nt < 8; nt++)
                    mma_bf16(acc[mi][nt], aHi[mi],
                             &bHi[nt >> 1][(nt & 1) * 2], acc[mi][nt]);
            #pragma unroll
            for (int mi = 0; mi < 2; mi++)
                #pragma unroll
                for (int nt = 0; nt < 8; nt++)
                    mma_bf16(acc[mi][nt], aHi[mi],
                             &bLo[nt >> 1][(nt & 1) * 2], acc[mi][nt]);
            #pragma unroll
            for (int mi = 0; mi < 2; mi++)
                #pragma unroll
                for (int nt = 0; nt < 8; nt++)
                    mma_bf16(acc[mi][nt], aLo[mi],
                             &bHi[nt >> 1][(nt & 1) * 2], acc[mi][nt]);
        }
    }

    const int er = lane >> 2;
    const int ec = (lane & 3) * 2;
    #pragma unroll
    for (int mi = 0; mi < 2; mi++) {
        int row0 = m0 + wm * 32 + mi * 16 + er;
        #pragma unroll
        for (int nt = 0; nt < 8; nt++) {
            int col = n0 + wn * 64 + nt * 8 + ec;
            float b0 = __ldg(bias + col), b1 = __ldg(bias + col + 1);
            if (OUT_SPLIT) {
                float v0 = (acc[mi][nt][0] + b0) * scale;
                float v1 = (acc[mi][nt][1] + b1) * scale;
                float v2 = (acc[mi][nt][2] + b0) * scale;
                float v3 = (acc[mi][nt][3] + b1) * scale;
                uint32_t h01, l01, h23, l23;
                pack_hilo(v0, v1, h01, l01);
                pack_hilo(v2, v3, h23, l23);
                *(uint32_t*)(Chi + (size_t)row0 * N + col) = h01;
                *(uint32_t*)(Clo + (size_t)row0 * N + col) = l01;
                *(uint32_t*)(Chi + (size_t)(row0 + 8) * N + col) = h23;
                *(uint32_t*)(Clo + (size_t)(row0 + 8) * N + col) = l23;
            } else {
                float2 o0 = make_float2(acc[mi][nt][0] + b0, acc[mi][nt][1] + b1);
                float2 o1 = make_float2(acc[mi][nt][2] + b0, acc[mi][nt][3] + b1);
                *(float2*)(Cf + (size_t)row0 * N + col) = o0;
                *(float2*)(Cf + (size_t)(row0 + 8) * N + col) = o1;
            }
        }
    }
}

// Fused QKV projection: region = blockIdx.x / 8.
__global__ void __launch_bounds__(256) gemm_qkv_kernel(
    const __nv_bfloat16* qin_hi, const __nv_bfloat16* qin_lo,
    const __nv_bfloat16* kin_hi, const __nv_bfloat16* kin_lo,
    const __nv_bfloat16* vin_hi, const __nv_bfloat16* vin_lo,
    const __nv_bfloat16* wq_hi, const __nv_bfloat16* wq_lo,
    const __nv_bfloat16* wk_hi, const __nv_bfloat16* wk_lo,
    const __nv_bfloat16* wv_hi, const __nv_bfloat16* wv_lo,
    const float* bq, const float* bk, const float* bv,
    __nv_bfloat16* Qhi, __nv_bfloat16* Qlo,
    __nv_bfloat16* Khi, __nv_bfloat16* Klo,
    __nv_bfloat16* Vhi, __nv_bfloat16* Vlo)
{
    extern __shared__ char sm[];
    const int region = blockIdx.x >> 3;
    const int n0 = (blockIdx.x & 7) * 128;
    const int m0 = blockIdx.y * 128;
    const __nv_bfloat16 *Ahi, *Alo, *Whi, *Wlo;
    const float* bias;
    __nv_bfloat16 *Chi, *Clo;
    float scale;
    if (region == 0) {
        Ahi = qin_hi; Alo = qin_lo; Whi = wq_hi; Wlo = wq_lo; bias = bq;
        Chi = Qhi; Clo = Qlo; scale = QSCALE;
    } else if (region == 1) {
        Ahi = kin_hi; Alo = kin_lo; Whi = wk_hi; Wlo = wk_lo; bias = bk;
        Chi = Khi; Clo = Klo; scale = 1.f;
    } else {
        Ahi = vin_hi; Alo = vin_lo; Whi = wv_hi; Wlo = wv_lo; bias = bv;
        Chi = Vhi; Clo = Vlo; scale = 1.f;
    }
    gemm_core<1>(sm, Ahi, Alo, Whi, Wlo, bias, nullptr, Chi, Clo, scale,
                 m0, n0, DM, DM);
}

// Output projection (fp32 out)
__global__ void __launch_bounds__(256) gemm_out_kernel(
    const __nv_bfloat16* Ahi, const __nv_bfloat16* Alo,
    const __nv_bfloat16* Whi, const __nv_bfloat16* Wlo,
    const float* bias, float* Cf)
{
    extern __shared__ char sm[];
    gemm_core<0>(sm, Ahi, Alo, Whi, Wlo, bias, Cf, nullptr, nullptr, 1.f,
                 blockIdx.y * 128, blockIdx.x * 128, DM, DM);
}

// ============================================================================
// Pre-split flash attention over COMPACTED keys. CTA = (b, h, 64 q-rows),
// 4 warps, KV tile 64, cp.async double-buffered, 3 CTAs/SM.
// ks-outer QK loop + half-interleaved passes: shorter MMA dependency chains.
// ============================================================================
#define AKV   9216
#define A_STG 36864
#define ATT_SMEM (2 * A_STG)   // 73728

__global__ void __launch_bounds__(128, 3) attn_ps_kernel(
    const __nv_bfloat16* __restrict__ qhi, const __nv_bfloat16* __restrict__ qlo,
    const __nv_bfloat16* __restrict__ khi, const __nv_bfloat16* __restrict__ klo,
    const __nv_bfloat16* __restrict__ vhi, const __nv_bfloat16* __restrict__ vlo,
    const int* __restrict__ nk,
    __nv_bfloat16* __restrict__ ohi, __nv_bfloat16* __restrict__ olo)
{
    extern __shared__ char sm[];
    const int b  = blockIdx.z;
    const int h  = blockIdx.y;
    const int q0 = blockIdx.x * 64;
    const int tid  = threadIdx.x;
    const int wid  = tid >> 5;    // 0..3
    const int lane = tid & 31;
    const uint32_t u = smem_u32(sm);

    const int nkb = nk[b];
    const int ntiles = (nkb + 63) >> 6;

    // ---- Phase 1: stage Q hi/lo (pre-scaled by 0.125*log2e at projection) ----
    {
        const __nv_bfloat16* const srcQ[2] = {qhi, qlo};
        #pragma unroll
        for (int half = 0; half < 2; half++)
            #pragma unroll
            for (int j = 0; j < 4; j++) {
                int cc = tid + j * 128;        // 512 chunks (64 rows x 8)
                int row = cc >> 3, ch = cc & 7;
                cp_async16(u + half * AKV + row * TSTRB + ch * 16,
                           srcQ[half] + (size_t)(b * SEQ + q0 + row) * DM + h * DH + ch * 8);
            }
        CP_COMMIT();
        CP_WAIT0();
        __syncthreads();
    }

    uint32_t qHi[4][4], qLo[4][4];
    {
        const uint32_t qrow = (uint32_t)(wid * 16 + (lane & 15));
        const uint32_t qkof = (uint32_t)((lane >> 4) * 8) * 2;
        #pragma unroll
        for (int ks = 0; ks < 4; ks++) {
            uint32_t addr = u + qrow * TSTRB + (uint32_t)(ks * 32) + qkof;
            ldmatrix_x4(qHi[ks], addr);
            ldmatrix_x4(qLo[ks], addr + AKV);
        }
    }
    __syncthreads();   // Q smem region reusable as KV stage 0

    const __nv_bfloat16* const srcKV[4] = {khi, klo, vhi, vlo};
    auto issue = [&](int j0, int s) {
        const uint32_t sb = u + s * A_STG;
        #pragma unroll
        for (int buf = 0; buf < 4; buf++)
            #pragma unroll
            for (int j = 0; j < 4; j++) {
                int cc = tid + j * 128;        // 512 chunks (64 rows x 8)
                int row = cc >> 3, ch = cc & 7;
                cp_async16(sb + buf * AKV + row * TSTRB + ch * 16,
                           srcKV[buf] + (size_t)(b * SEQ + j0 + row) * DM + h * DH + ch * 8);
            }
    };

    // ---- main loop state ----
    float m0 = -1e30f, m1 = -1e30f, l0 = 0.f, l1 = 0.f;
    float oAcc[8][4];
    #pragma unroll
    for (int nt = 0; nt < 8; nt++)
        #pragma unroll
        for (int t = 0; t < 4; t++) oAcc[nt][t] = 0.f;

    const uint32_t krow_b = (uint32_t)((lane & 7) + ((lane >> 4) & 1) * 8);
    const uint32_t kk_b   = (uint32_t)(((lane >> 3) & 1) * 8) * 2;
    const uint32_t vrow_b = (uint32_t)(lane & 15);
    const uint32_t vcol_b = (uint32_t)(((lane >> 4) & 1) * 8) * 2;
    const int mcol = (lane & 3) * 2;

    issue(0, 0); CP_COMMIT();

    for (int t = 0; t < ntiles; ++t) {
        const int cur = t & 1;
        CP_WAIT0();
        __syncthreads();
        if (t + 1 < ntiles) { issue((t + 1) * 64, cur ^ 1); CP_COMMIT(); }

        const uint32_t sb = u + cur * A_STG;

        // ---- S = Q @ K^T (3 passes; ks-outer, halves interleaved) ----
        float sAcc[8][4];
        #pragma unroll
        for (int nt = 0; nt < 8; nt++)
            #pragma unroll
            for (int tt = 0; tt < 4; tt++) sAcc[nt][tt] = 0.f;

        #pragma unroll
        for (int ks = 0; ks < 4; ks++) {
            const uint32_t kbyte = (uint32_t)(ks * 16) * 2;
            #pragma unroll
            for (int nt2 = 0; nt2 < 4; nt2++) {
                uint32_t kH[4], kL[4];
                uint32_t addr = sb + (uint32_t)(nt2 * 16 + krow_b) * TSTRB + kbyte + kk_b;
                ldmatrix_x4(kH, addr);
                ldmatrix_x4(kL, addr + AKV);
                float* d0 = sAcc[nt2 * 2];
                float* d1 = sAcc[nt2 * 2 + 1];
                mma_bf16(d0, qHi[ks], &kH[0], d0);
                mma_bf16(d1, qHi[ks], &kH[2], d1);
                mma_bf16(d0, qHi[ks], &kL[0], d0);
                mma_bf16(d1, qHi[ks], &kL[2], d1);
                mma_bf16(d0, qLo[ks], &kH[0], d0);
                mma_bf16(d1, qLo[ks], &kH[2], d1);
            }
        }

        // ---- tail masking (uniform branch; only last partial tile) ----
        if (t == ntiles - 1 && (nkb & 63) != 0) {
            const int lim = nkb - t * 64;   // 1..63
            #pragma unroll
            for (int nt = 0; nt < 8; nt++) {
                int c0 = nt * 8 + mcol;
                if (c0 >= lim)     { sAcc[nt][0] = MASKED; sAcc[nt][2] = MASKED; }
                if (c0 + 1 >= lim) { sAcc[nt][1] = MASKED; sAcc[nt][3] = MASKED; }
            }
        }

        // ---- online softmax (base-2 domain) ----
        float rm0 = -1e30f, rm1 = -1e30f;
        #pragma unroll
        for (int nt = 0; nt < 8; nt++) {
            rm0 = fmaxf(rm0, fmaxf(sAcc[nt][0], sAcc[nt][1]));
            rm1 = fmaxf(rm1, fmaxf(sAcc[nt][2], sAcc[nt][3]));
        }
        rm0 = fmaxf(rm0, __shfl_xor_sync(0xffffffffu, rm0, 1));
        rm0 = fmaxf(rm0, __shfl_xor_sync(0xffffffffu, rm0, 2));
        rm1 = fmaxf(rm1, __shfl_xor_sync(0xffffffffu, rm1, 1));
        rm1 = fmaxf(rm1, __shfl_xor_sync(0xffffffffu, rm1, 2));

        float m0n = fmaxf(m0, rm0), m1n = fmaxf(m1, rm1);
        float a0 = exp2f(m0 - m0n), a1 = exp2f(m1 - m1n);
        float ps0 = 0.f, ps1 = 0.f;
        #pragma unroll
        for (int nt = 0; nt < 8; nt++) {
            float p0 = exp2f(sAcc[nt][0] - m0n);
            float p1 = exp2f(sAcc[nt][1] - m0n);
            float p2 = exp2f(sAcc[nt][2] - m1n);
            float p3 = exp2f(sAcc[nt][3] - m1n);
            sAcc[nt][0] = p0; sAcc[nt][1] = p1; sAcc[nt][2] = p2; sAcc[nt][3] = p3;
            ps0 += p0 + p1; ps1 += p2 + p3;
            oAcc[nt][0] *= a0; oAcc[nt][1] *= a0;
            oAcc[nt][2] *= a1; oAcc[nt][3] *= a1;
        }
        ps0 += __shfl_xor_sync(0xffffffffu, ps0, 1);
        ps0 += __shfl_xor_sync(0xffffffffu, ps0, 2);
        ps1 += __shfl_xor_sync(0xffffffffu, ps1, 1);
        ps1 += __shfl_xor_sync(0xffffffffu, ps1, 2);
        l0 = l0 * a0 + ps0;
        l1 = l1 * a1 + ps1;
        m0 = m0n; m1 = m1n;

        // ---- O += P @ V (3 passes; halves interleaved) ----
        #pragma unroll
        for (int ks = 0; ks < 4; ks++) {
            uint32_t aH[4], aL[4];
            pack_hilo(sAcc[2 * ks][0],     sAcc[2 * ks][1],     aH[0], aL[0]);
            pack_hilo(sAcc[2 * ks][2],     sAcc[2 * ks][3],     aH[1], aL[1]);
            pack_hilo(sAcc[2 * ks + 1][0], sAcc[2 * ks + 1][1], aH[2], aL[2]);
            pack_hilo(sAcc[2 * ks + 1][2], sAcc[2 * ks + 1][3], aH[3], aL[3]);

            #pragma unroll
            for (int nt2 = 0; nt2 < 4; nt2++) {
                uint32_t vH[4], vL[4];
                uint32_t addr = sb + 2 * AKV + (uint32_t)(ks * 16 + vrow_b) * TSTRB
                              + (uint32_t)(nt2 * 16) * 2 + vcol_b;
                ldmatrix_x4_trans(vH, addr);
                ldmatrix_x4_trans(vL, addr + AKV);
                float* d0 = oAcc[nt2 * 2];
                float* d1 = oAcc[nt2 * 2 + 1];
                mma_bf16(d0, aH, &vH[0], d0);
                mma_bf16(d1, aH, &vH[2], d1);
                mma_bf16(d0, aL, &vH[0], d0);
                mma_bf16(d1, aL, &vH[2], d1);
                mma_bf16(d0, aH, &vL[0], d0);
                mma_bf16(d1, aH, &vL[2], d1);
            }
        }
    }

    // ---- epilogue: write split bf16 attention output ----
    float i0 = 1.f / l0, i1 = 1.f / l1;
    const int r  = lane >> 2;
    const int c2 = (lane & 3) * 2;
    const int row0 = q0 + wid * 16 + r;
    #pragma unroll
    for (int nt = 0; nt < 8; nt++) {
        int col = h * DH + nt * 8 + c2;
        uint32_t h01, l01, h23, l23;
        pack_hilo(oAcc[nt][0] * i0, oAcc[nt][1] * i0, h01, l01);
        pack_hilo(oAcc[nt][2] * i1, oAcc[nt][3] * i1, h23, l23);
        *(uint32_t*)(ohi + (size_t)(b * SEQ + row0) * DM + col) = h01;
        *(uint32_t*)(olo + (size_t)(b * SEQ + row0) * DM + col) = l01;
        *(uint32_t*)(ohi + (size_t)(b * SEQ + row0 + 8) * DM + col) = h23;
        *(uint32_t*)(olo + (size_t)(b * SEQ + row0 + 8) * DM + col) = l23;
    }
}

// ---------------------------------------------------------------------------
extern "C" void kernel_launch(void* const* d_in, const int* in_sizes, int n_in,
                              void* d_out, int out_size) {
    const float* query = (const float*)d_in[0];
    const float* key_t = (const float*)d_in[1];
    const float* value = (const float*)d_in[2];
    const int*   mask  = (const int*)  d_in[3];
    const float* Wq = (const float*)d_in[4];
    const float* bq = (const float*)d_in[5];
    const float* Wk = (const float*)d_in[6];
    const float* bk = (const float*)d_in[7];
    const float* Wv = (const float*)d_in[8];
    const float* bv = (const float*)d_in[9];
    const float* Wo = (const float*)d_in[10];
    const float* bo = (const float*)d_in[11];
    float* out = (float*)d_out;

    __nv_bfloat16 *qin_hi, *qin_lo, *kin_hi, *kin_lo, *vin_hi, *vin_lo;
    __nv_bfloat16 *wq_hi, *wq_lo, *wk_hi, *wk_lo, *wv_hi, *wv_lo, *wo_hi, *wo_lo;
    __nv_bfloat16 *Q_hi, *Q_lo, *K_hi, *K_lo, *V_hi, *V_lo, *at_hi, *at_lo;
    __nv_bfloat16 *Kc_hi, *Kc_lo, *Vc_hi, *Vc_lo;
    int *idxp, *nkp;
    cudaGetSymbolAddress((void**)&qin_hi, g_qin_hi);
    cudaGetSymbolAddress((void**)&qin_lo, g_qin_lo);
    cudaGetSymbolAddress((void**)&kin_hi, g_kin_hi);
    cudaGetSymbolAddress((void**)&kin_lo, g_kin_lo);
    cudaGetSymbolAddress((void**)&vin_hi, g_vin_hi);
    cudaGetSymbolAddress((void**)&vin_lo, g_vin_lo);
    cudaGetSymbolAddress((void**)&wq_hi, g_wq_hi);
    cudaGetSymbolAddress((void**)&wq_lo, g_wq_lo);
    cudaGetSymbolAddress((void**)&wk_hi, g_wk_hi);
    cudaGetSymbolAddress((void**)&wk_lo, g_wk_lo);
    cudaGetSymbolAddress((void**)&wv_hi, g_wv_hi);
    cudaGetSymbolAddress((void**)&wv_lo, g_wv_lo);
    cudaGetSymbolAddress((void**)&wo_hi, g_wo_hi);
    cudaGetSymbolAddress((void**)&wo_lo, g_wo_lo);
    cudaGetSymbolAddress((void**)&Q_hi, g_Q_hi);
    cudaGetSymbolAddress((void**)&Q_lo, g_Q_lo);
    cudaGetSymbolAddress((void**)&K_hi, g_K_hi);
    cudaGetSymbolAddress((void**)&K_lo, g_K_lo);
    cudaGetSymbolAddress((void**)&V_hi, g_V_hi);
    cudaGetSymbolAddress((void**)&V_lo, g_V_lo);
    cudaGetSymbolAddress((void**)&at_hi, g_at_hi);
    cudaGetSymbolAddress((void**)&at_lo, g_at_lo);
    cudaGetSymbolAddress((void**)&Kc_hi, g_Kc_hi);
    cudaGetSymbolAddress((void**)&Kc_lo, g_Kc_lo);
    cudaGetSymbolAddress((void**)&Vc_hi, g_Vc_hi);
    cudaGetSymbolAddress((void**)&Vc_lo, g_Vc_lo);
    cudaGetSymbolAddress((void**)&idxp, g_idx);
    cudaGetSymbolAddress((void**)&nkp, g_nk);

    const int M = BATCH * SEQ;       // 4096
    const int n4m = MELEMS / 4;
    const int n4w = WELEMS / 4;

    cudaFuncSetAttribute(gemm_qkv_kernel,
                         cudaFuncAttributeMaxDynamicSharedMemorySize, GEMM_PS_SMEM);
    cudaFuncSetAttribute(gemm_out_kernel,
                         cudaFuncAttributeMaxDynamicSharedMemorySize, GEMM_PS_SMEM);
    cudaFuncSetAttribute(attn_ps_kernel,
                         cudaFuncAttributeMaxDynamicSharedMemorySize, ATT_SMEM);

    // Pre-pass splits (region-batched) + mask index scan
    dim3 s3grid((n4m + 255) / 256, 3);
    split3_kernel<<<s3grid, 256>>>((const float4*)query, (const float4*)key_t,
                                   (const float4*)value,
                                   (uint2*)qin_hi, (uint2*)qin_lo,
                                   (uint2*)kin_hi, (uint2*)kin_lo,
                                   (uint2*)vin_hi, (uint2*)vin_lo, n4m);
    dim3 s4grid((n4w + 255) / 256, 4);
    split4_kernel<<<s4grid, 256>>>((const float4*)Wq, (const float4*)Wk,
                                   (const float4*)Wv, (const float4*)Wo,
                                   (uint2*)wq_hi, (uint2*)wq_lo,
                                   (uint2*)wk_hi, (uint2*)wk_lo,
                                   (uint2*)wv_hi, (uint2*)wv_lo,
                                   (uint2*)wo_hi, (uint2*)wo_lo, n4w);
    mask_compact_idx<<<BATCH, 32>>>(mask, idxp, nkp);

    // Fused QKV projections
    dim3 qkvgrid(24, M / 128);
    gemm_qkv_kernel<<<qkvgrid, 256, GEMM_PS_SMEM>>>(
        qin_hi, qin_lo, kin_hi, kin_lo, vin_hi, vin_lo,
        wq_hi, wq_lo, wk_hi, wk_lo, wv_hi, wv_lo,
        bq, bk, bv, Q_hi, Q_lo, K_hi, K_lo, V_hi, V_lo);

    // Compact K/V rows to unmasked keys
    dim3 ggrid2(SEQ, BATCH);
    gather_kv<<<ggrid2, 128>>>((const uint4*)K_hi, (const uint4*)K_lo,
                               (const uint4*)V_hi, (const uint4*)V_lo,
                               (uint4*)Kc_hi, (uint4*)Kc_lo,
                               (uint4*)Vc_hi, (uint4*)Vc_lo, idxp, nkp);

    dim3 agrid(SEQ / 64, NH, BATCH); // (32, 16, 2)
    attn_ps_kernel<<<agrid, 128, ATT_SMEM>>>(Q_hi, Q_lo, Kc_hi, Kc_lo, Vc_hi, Vc_lo,
                                             nkp, at_hi, at_lo);

    dim3 ogrid(DM / 128, M / 128);   // (8, 32)
    gemm_out_kernel<<<ogrid, 256, GEMM_PS_SMEM>>>(at_hi, at_lo, wo_hi, wo_lo, bo, out);
}

// round 17
// speedup vs baseline: 1.0577x; 1.0577x over previous
#include <cuda_runtime.h>
#include <cuda_bf16.h>
#include <stdint.h>
#include <math.h>

#define BATCH 2
#define SEQ   2048
#define DM    1024
#define NH    16
#define DH    64
#define MELEMS (BATCH*SEQ*DM)   // 4194304
#define WELEMS (DM*DM)          // 1048576

#define QSCALE 0.18033688f      // 0.125 * log2(e)
#define MASKED (-1.44269504e9f) // -1e9 * log2(e)

// ---- split-bf16 scratch (allocation-free rule: __device__ globals) ----
__device__ __nv_bfloat16 g_qin_hi[MELEMS], g_qin_lo[MELEMS];
__device__ __nv_bfloat16 g_kin_hi[MELEMS], g_kin_lo[MELEMS];
__device__ __nv_bfloat16 g_vin_hi[MELEMS], g_vin_lo[MELEMS];
__device__ __nv_bfloat16 g_wq_hi[WELEMS], g_wq_lo[WELEMS];
__device__ __nv_bfloat16 g_wk_hi[WELEMS], g_wk_lo[WELEMS];
__device__ __nv_bfloat16 g_wv_hi[WELEMS], g_wv_lo[WELEMS];
__device__ __nv_bfloat16 g_wo_hi[WELEMS], g_wo_lo[WELEMS];
__device__ __nv_bfloat16 g_Q_hi[MELEMS], g_Q_lo[MELEMS];
__device__ __nv_bfloat16 g_K_hi[MELEMS], g_K_lo[MELEMS];
__device__ __nv_bfloat16 g_V_hi[MELEMS], g_V_lo[MELEMS];
__device__ __nv_bfloat16 g_at_hi[MELEMS], g_at_lo[MELEMS];
// compacted K/V (unmasked keys only)
__device__ __nv_bfloat16 g_Kc_hi[MELEMS], g_Kc_lo[MELEMS];
__device__ __nv_bfloat16 g_Vc_hi[MELEMS], g_Vc_lo[MELEMS];
__device__ int g_idx[BATCH*SEQ];
__device__ int g_nk[BATCH];

// ============================================================================
// Helpers
// ============================================================================
__device__ __forceinline__ uint32_t smem_u32(const void* p) {
    uint32_t a;
    asm("{ .reg .u64 t; cvta.to.shared.u64 t, %1; cvt.u32.u64 %0, t; }"
        : "=r"(a) : "l"(p));
    return a;
}
__device__ __forceinline__ void cp_async16(uint32_t dst, const void* src) {
    asm volatile("cp.async.cg.shared.global [%0], [%1], 16;"
                 :: "r"(dst), "l"(src) : "memory");
}
#define CP_COMMIT() asm volatile("cp.async.commit_group;" ::: "memory")
#define CP_WAIT0()  asm volatile("cp.async.wait_group 0;" ::: "memory")

__device__ __forceinline__ void ldmatrix_x4(uint32_t* r, uint32_t addr) {
    asm volatile("ldmatrix.sync.aligned.m8n8.x4.shared.b16 {%0,%1,%2,%3}, [%4];"
                 : "=r"(r[0]), "=r"(r[1]), "=r"(r[2]), "=r"(r[3]) : "r"(addr));
}
__device__ __forceinline__ void ldmatrix_x4_trans(uint32_t* r, uint32_t addr) {
    asm volatile("ldmatrix.sync.aligned.m8n8.x4.trans.shared.b16 {%0,%1,%2,%3}, [%4];"
                 : "=r"(r[0]), "=r"(r[1]), "=r"(r[2]), "=r"(r[3]) : "r"(addr));
}
__device__ __forceinline__ void mma_bf16(float* d, const uint32_t* a, const uint32_t* b,
                                         const float* c) {
    asm volatile(
        "mma.sync.aligned.m16n8k16.row.col.f32.bf16.bf16.f32 "
        "{%0,%1,%2,%3}, {%4,%5,%6,%7}, {%8,%9}, {%10,%11,%12,%13};"
        : "=f"(d[0]), "=f"(d[1]), "=f"(d[2]), "=f"(d[3])
        : "r"(a[0]), "r"(a[1]), "r"(a[2]), "r"(a[3]),
          "r"(b[0]), "r"(b[1]),
          "f"(c[0]), "f"(c[1]), "f"(c[2]), "f"(c[3]));
}

__device__ __forceinline__ uint32_t cvt_bf16x2(float x, float y) {
    uint32_t r;
    asm("cvt.rn.bf16x2.f32 %0, %1, %2;" : "=r"(r) : "f"(y), "f"(x));
    return r;
}
__device__ __forceinline__ void pack_hilo(float x, float y, uint32_t& hi, uint32_t& lo) {
    hi = cvt_bf16x2(x, y);
    float fx = __uint_as_float(hi << 16);
    float fy = __uint_as_float(hi & 0xffff0000u);
    lo = cvt_bf16x2(x - fx, y - fy);
}

#define TSTRB 144   // 9 * 16B: conflict-free, 16B-aligned rows

// ============================================================================
// Pre-pass: fp32 -> hi/lo bf16 split (region-batched)
// ============================================================================
__global__ void split3_kernel(const float4* s0, const float4* s1, const float4* s2,
                              uint2* h0, uint2* l0, uint2* h1, uint2* l1,
                              uint2* h2, uint2* l2, int n4) {
    int i = blockIdx.x * 256 + threadIdx.x;
    if (i >= n4) return;
    int r = blockIdx.y;
    const float4* s = (r == 0) ? s0 : (r == 1) ? s1 : s2;
    uint2* hd = (r == 0) ? h0 : (r == 1) ? h1 : h2;
    uint2* ld = (r == 0) ? l0 : (r == 1) ? l1 : l2;
    float4 v = s[i];
    uint2 hp, lp;
    pack_hilo(v.x, v.y, hp.x, lp.x);
    pack_hilo(v.z, v.w, hp.y, lp.y);
    hd[i] = hp; ld[i] = lp;
}

__global__ void split4_kernel(const float4* s0, const float4* s1,
                              const float4* s2, const float4* s3,
                              uint2* h0, uint2* l0, uint2* h1, uint2* l1,
                              uint2* h2, uint2* l2, uint2* h3, uint2* l3, int n4) {
    int i = blockIdx.x * 256 + threadIdx.x;
    if (i >= n4) return;
    int r = blockIdx.y;
    const float4* s = (r == 0) ? s0 : (r == 1) ? s1 : (r == 2) ? s2 : s3;
    uint2* hd = (r == 0) ? h0 : (r == 1) ? h1 : (r == 2) ? h2 : h3;
    uint2* ld = (r == 0) ? l0 : (r == 1) ? l1 : (r == 2) ? l2 : l3;
    float4 v = s[i];
    uint2 hp, lp;
    pack_hilo(v.x, v.y, hp.x, lp.x);
    pack_hilo(v.z, v.w, hp.y, lp.y);
    hd[i] = hp; ld[i] = lp;
}

// ============================================================================
// Mask compaction: idx[b][r] = r-th unmasked key position; nk[b] = count.
// ============================================================================
__global__ void mask_compact_idx(const int* __restrict__ mask,
                                 int* __restrict__ idx, int* __restrict__ nk) {
    const int b = blockIdx.x;
    const int lane = threadIdx.x;   // 32 threads
    int base = 0;
    for (int i = 0; i < SEQ; i += 32) {
        int m = mask[b * SEQ + i + lane] != 0;
        unsigned bal = __ballot_sync(0xffffffffu, m);
        int pos = base + __popc(bal & ((1u << lane) - 1u));
        if (m) idx[b * SEQ + pos] = i + lane;
        base += __popc(bal);
    }
    if (lane == 0) nk[b] = base;
}

// Gather K/V hi/lo rows into compacted buffers; zero-fill to 64-row multiple.
__global__ void gather_kv(const uint4* __restrict__ khi, const uint4* __restrict__ klo,
                          const uint4* __restrict__ vhi, const uint4* __restrict__ vlo,
                          uint4* __restrict__ kchi, uint4* __restrict__ kclo,
                          uint4* __restrict__ vchi, uint4* __restrict__ vclo,
                          const int* __restrict__ idx, const int* __restrict__ nk) {
    const int r = blockIdx.x;
    const int b = blockIdx.y;
    const int n = nk[b];
    const int rt = (n + 63) & ~63;
    if (r >= rt) return;
    const int tid = threadIdx.x;     // 128, DM/8 = 128 uint4 per row
    const size_t drow = ((size_t)(b * SEQ + r)) * (DM / 8) + tid;
    if (r < n) {
        const size_t srow = ((size_t)(b * SEQ + idx[b * SEQ + r])) * (DM / 8) + tid;
        kchi[drow] = khi[srow];
        kclo[drow] = klo[srow];
        vchi[drow] = vhi[srow];
        vclo[drow] = vlo[srow];
    } else {
        uint4 z = make_uint4(0, 0, 0, 0);
        kchi[drow] = z; kclo[drow] = z; vchi[drow] = z; vclo[drow] = z;
    }
}

// ============================================================================
// Pre-split GEMM core:  C[M,N] = (A @ W^T + bias) * scale
// 128x64 CTA tile, K-chunk 64, cp.async double buffer, 3-pass split-bf16.
// 2 CTAs/SM (stage 54KB x2 = 108KB smem, regs capped at 128).
// Stage layout (55296 B): Ahi +0, Alo +18432, Bhi +36864, Blo +46080.
// ============================================================================
#define G_STG   55296
#define GEMM_PS_SMEM (2 * G_STG)   // 110592

template<int OUT_SPLIT>
__device__ __forceinline__ void gemm_core(
    char* sm,
    const __nv_bfloat16* __restrict__ Ahi, const __nv_bfloat16* __restrict__ Alo,
    const __nv_bfloat16* __restrict__ Whi, const __nv_bfloat16* __restrict__ Wlo,
    const float* __restrict__ bias,
    float* __restrict__ Cf, __nv_bfloat16* __restrict__ Chi, __nv_bfloat16* __restrict__ Clo,
    float scale, int m0, int n0, int N, int K)
{
    const int tid = threadIdx.x;
    const int wid = tid >> 5;
    const int lane = tid & 31;
    const int wm = wid >> 1;          // 0..3 -> 32-row slice
    const int wn = wid & 1;           // 0..1 -> 32-col slice
    const uint32_t u = smem_u32(sm);

    const __nv_bfloat16* const srcA[2] = {Ahi, Alo};
    const __nv_bfloat16* const srcB[2] = {Whi, Wlo};

    auto issue = [&](int c, int s) {
        const int k0 = c * 64;
        const uint32_t sb = u + s * G_STG;
        // A: 128 rows x 8 chunks x 2 halves = 2048 -> 8 per thread
        #pragma unroll
        for (int half = 0; half < 2; half++)
            #pragma unroll
            for (int j = 0; j < 4; j++) {
                int cc = tid + j * 256;
                int row = cc >> 3, ch = cc & 7;
                cp_async16(sb + half * 18432 + row * TSTRB + ch * 16,
                           srcA[half] + (size_t)(m0 + row) * K + k0 + ch * 8);
            }
        // B: 64 rows x 8 chunks x 2 halves = 1024 -> 4 per thread
        #pragma unroll
        for (int half = 0; half < 2; half++)
            #pragma unroll
            for (int j = 0; j < 2; j++) {
                int cc = tid + j * 256;
                int row = cc >> 3, ch = cc & 7;
                cp_async16(sb + 36864 + half * 9216 + row * TSTRB + ch * 16,
                           srcB[half] + (size_t)(n0 + row) * K + k0 + ch * 8);
            }
    };

    float acc[2][4][4];
    #pragma unroll
    for (int i = 0; i < 2; i++)
        #pragma unroll
        for (int j = 0; j < 4; j++)
            #pragma unroll
            for (int t = 0; t < 4; t++) acc[i][j][t] = 0.f;

    const uint32_t a_row = (uint32_t)(wm * 32 + (lane & 15));
    const uint32_t a_kof = (uint32_t)((lane >> 4) * 8) * 2;
    const uint32_t b_row = (uint32_t)(wn * 32 + (lane & 7) + ((lane >> 4) & 1) * 8);
    const uint32_t b_kof = (uint32_t)(((lane >> 3) & 1) * 8) * 2;

    issue(0, 0); CP_COMMIT();

    const int nchunk = K / 64;
    for (int c = 0; c < nchunk; ++c) {
        const int cur = c & 1;
        CP_WAIT0();
        __syncthreads();
        if (c + 1 < nchunk) { issue(c + 1, cur ^ 1); CP_COMMIT(); }

        const uint32_t sb = u + cur * G_STG;
        #pragma unroll
        for (int ks = 0; ks < 4; ks++) {
            const uint32_t kbyte = (uint32_t)(ks * 16) * 2;
            uint32_t aHi[2][4], aLo[2][4], bHi[2][4], bLo[2][4];
            #pragma unroll
            for (int mi = 0; mi < 2; mi++) {
                uint32_t ar = sb + (a_row + mi * 16) * TSTRB + kbyte + a_kof;
                ldmatrix_x4(aHi[mi], ar);
                ldmatrix_x4(aLo[mi], ar + 18432);
            }
            #pragma unroll
            for (int nt2 = 0; nt2 < 2; nt2++) {
                uint32_t br = sb + 36864 + (b_row + nt2 * 16) * TSTRB + kbyte + b_kof;
                ldmatrix_x4(bHi[nt2], br);
                ldmatrix_x4(bLo[nt2], br + 9216);
            }
            #pragma unroll
            for (int mi = 0; mi < 2; mi++)
                #pragma unroll
                for (int nt = 0; nt < 4; nt++) {
                    const uint32_t* bh = &bHi[nt >> 1][(nt & 1) * 2];
                    const uint32_t* bl = &bLo[nt >> 1][(nt & 1) * 2];
                    mma_bf16(acc[mi][nt], aHi[mi], bh, acc[mi][nt]);
                    mma_bf16(acc[mi][nt], aHi[mi], bl, acc[mi][nt]);
                    mma_bf16(acc[mi][nt], aLo[mi], bh, acc[mi][nt]);
                }
        }
    }

    const int er = lane >> 2;
    const int ec = (lane & 3) * 2;
    #pragma unroll
    for (int mi = 0; mi < 2; mi++) {
        int row0 = m0 + wm * 32 + mi * 16 + er;
        #pragma unroll
        for (int nt = 0; nt < 4; nt++) {
            int col = n0 + wn * 32 + nt * 8 + ec;
            float b0 = __ldg(bias + col), b1 = __ldg(bias + col + 1);
            if (OUT_SPLIT) {
                float v0 = (acc[mi][nt][0] + b0) * scale;
                float v1 = (acc[mi][nt][1] + b1) * scale;
                float v2 = (acc[mi][nt][2] + b0) * scale;
                float v3 = (acc[mi][nt][3] + b1) * scale;
                uint32_t h01, l01, h23, l23;
                pack_hilo(v0, v1, h01, l01);
                pack_hilo(v2, v3, h23, l23);
                *(uint32_t*)(Chi + (size_t)row0 * N + col) = h01;
                *(uint32_t*)(Clo + (size_t)row0 * N + col) = l01;
                *(uint32_t*)(Chi + (size_t)(row0 + 8) * N + col) = h23;
                *(uint32_t*)(Clo + (size_t)(row0 + 8) * N + col) = l23;
            } else {
                float2 o0 = make_float2(acc[mi][nt][0] + b0, acc[mi][nt][1] + b1);
                float2 o1 = make_float2(acc[mi][nt][2] + b0, acc[mi][nt][3] + b1);
                *(float2*)(Cf + (size_t)row0 * N + col) = o0;
                *(float2*)(Cf + (size_t)(row0 + 8) * N + col) = o1;
            }
        }
    }
}

// Fused QKV projection: region = blockIdx.x / 16 (16 n-blocks of 64).
__global__ void __launch_bounds__(256, 2) gemm_qkv_kernel(
    const __nv_bfloat16* qin_hi, const __nv_bfloat16* qin_lo,
    const __nv_bfloat16* kin_hi, const __nv_bfloat16* kin_lo,
    const __nv_bfloat16* vin_hi, const __nv_bfloat16* vin_lo,
    const __nv_bfloat16* wq_hi, const __nv_bfloat16* wq_lo,
    const __nv_bfloat16* wk_hi, const __nv_bfloat16* wk_lo,
    const __nv_bfloat16* wv_hi, const __nv_bfloat16* wv_lo,
    const float* bq, const float* bk, const float* bv,
    __nv_bfloat16* Qhi, __nv_bfloat16* Qlo,
    __nv_bfloat16* Khi, __nv_bfloat16* Klo,
    __nv_bfloat16* Vhi, __nv_bfloat16* Vlo)
{
    extern __shared__ char sm[];
    const int region = blockIdx.x >> 4;
    const int n0 = (blockIdx.x & 15) * 64;
    const int m0 = blockIdx.y * 128;
    const __nv_bfloat16 *Ahi, *Alo, *Whi, *Wlo;
    const float* bias;
    __nv_bfloat16 *Chi, *Clo;
    float scale;
    if (region == 0) {
        Ahi = qin_hi; Alo = qin_lo; Whi = wq_hi; Wlo = wq_lo; bias = bq;
        Chi = Qhi; Clo = Qlo; scale = QSCALE;
    } else if (region == 1) {
        Ahi = kin_hi; Alo = kin_lo; Whi = wk_hi; Wlo = wk_lo; bias = bk;
        Chi = Khi; Clo = Klo; scale = 1.f;
    } else {
        Ahi = vin_hi; Alo = vin_lo; Whi = wv_hi; Wlo = wv_lo; bias = bv;
        Chi = Vhi; Clo = Vlo; scale = 1.f;
    }
    gemm_core<1>(sm, Ahi, Alo, Whi, Wlo, bias, nullptr, Chi, Clo, scale,
                 m0, n0, DM, DM);
}

// Output projection (fp32 out)
__global__ void __launch_bounds__(256, 2) gemm_out_kernel(
    const __nv_bfloat16* Ahi, const __nv_bfloat16* Alo,
    const __nv_bfloat16* Whi, const __nv_bfloat16* Wlo,
    const float* bias, float* Cf)
{
    extern __shared__ char sm[];
    gemm_core<0>(sm, Ahi, Alo, Whi, Wlo, bias, Cf, nullptr, nullptr, 1.f,
                 blockIdx.y * 128, blockIdx.x * 64, DM, DM);
}

// ============================================================================
// Pre-split flash attention over COMPACTED keys. CTA = (b, h, 64 q-rows),
// 4 warps, KV tile 64, cp.async double-buffered, 3 CTAs/SM. (R14 proven)
// ============================================================================
#define AKV   9216
#define A_STG 36864
#define ATT_SMEM (2 * A_STG)   // 73728

__global__ void __launch_bounds__(128, 3) attn_ps_kernel(
    const __nv_bfloat16* __restrict__ qhi, const __nv_bfloat16* __restrict__ qlo,
    const __nv_bfloat16* __restrict__ khi, const __nv_bfloat16* __restrict__ klo,
    const __nv_bfloat16* __restrict__ vhi, const __nv_bfloat16* __restrict__ vlo,
    const int* __restrict__ nk,
    __nv_bfloat16* __restrict__ ohi, __nv_bfloat16* __restrict__ olo)
{
    extern __shared__ char sm[];
    const int b  = blockIdx.z;
    const int h  = blockIdx.y;
    const int q0 = blockIdx.x * 64;
    const int tid  = threadIdx.x;
    const int wid  = tid >> 5;    // 0..3
    const int lane = tid & 31;
    const uint32_t u = smem_u32(sm);

    const int nkb = nk[b];
    const int ntiles = (nkb + 63) >> 6;

    // ---- Phase 1: stage Q hi/lo (pre-scaled by 0.125*log2e at projection) ----
    {
        const __nv_bfloat16* const srcQ[2] = {qhi, qlo};
        #pragma unroll
        for (int half = 0; half < 2; half++)
            #pragma unroll
            for (int j = 0; j < 4; j++) {
                int cc = tid + j * 128;        // 512 chunks (64 rows x 8)
                int row = cc >> 3, ch = cc & 7;
                cp_async16(u + half * AKV + row * TSTRB + ch * 16,
                           srcQ[half] + (size_t)(b * SEQ + q0 + row) * DM + h * DH + ch * 8);
            }
        CP_COMMIT();
        CP_WAIT0();
        __syncthreads();
    }

    uint32_t qHi[4][4], qLo[4][4];
    {
        const uint32_t qrow = (uint32_t)(wid * 16 + (lane & 15));
        const uint32_t qkof = (uint32_t)((lane >> 4) * 8) * 2;
        #pragma unroll
        for (int ks = 0; ks < 4; ks++) {
            uint32_t addr = u + qrow * TSTRB + (uint32_t)(ks * 32) + qkof;
            ldmatrix_x4(qHi[ks], addr);
            ldmatrix_x4(qLo[ks], addr + AKV);
        }
    }
    __syncthreads();   // Q smem region reusable as KV stage 0

    const __nv_bfloat16* const srcKV[4] = {khi, klo, vhi, vlo};
    auto issue = [&](int j0, int s) {
        const uint32_t sb = u + s * A_STG;
        #pragma unroll
        for (int buf = 0; buf < 4; buf++)
            #pragma unroll
            for (int j = 0; j < 4; j++) {
                int cc = tid + j * 128;        // 512 chunks (64 rows x 8)
                int row = cc >> 3, ch = cc & 7;
                cp_async16(sb + buf * AKV + row * TSTRB + ch * 16,
                           srcKV[buf] + (size_t)(b * SEQ + j0 + row) * DM + h * DH + ch * 8);
            }
    };

    // ---- main loop state ----
    float m0 = -1e30f, m1 = -1e30f, l0 = 0.f, l1 = 0.f;
    float oAcc[8][4];
    #pragma unroll
    for (int nt = 0; nt < 8; nt++)
        #pragma unroll
        for (int t = 0; t < 4; t++) oAcc[nt][t] = 0.f;

    const uint32_t krow_b = (uint32_t)((lane & 7) + ((lane >> 4) & 1) * 8);
    const uint32_t kk_b   = (uint32_t)(((lane >> 3) & 1) * 8) * 2;
    const uint32_t vrow_b = (uint32_t)(lane & 15);
    const uint32_t vcol_b = (uint32_t)(((lane >> 4) & 1) * 8) * 2;
    const int mcol = (lane & 3) * 2;

    issue(0, 0); CP_COMMIT();

    for (int t = 0; t < ntiles; ++t) {
        const int cur = t & 1;
        CP_WAIT0();
        __syncthreads();
        if (t + 1 < ntiles) { issue((t + 1) * 64, cur ^ 1); CP_COMMIT(); }

        const uint32_t sb = u + cur * A_STG;

        // ---- S = Q @ K^T (3 passes; ks-outer, halves interleaved) ----
        float sAcc[8][4];
        #pragma unroll
        for (int nt = 0; nt < 8; nt++)
            #pragma unroll
            for (int tt = 0; tt < 4; tt++) sAcc[nt][tt] = 0.f;

        #pragma unroll
        for (int ks = 0; ks < 4; ks++) {
            const uint32_t kbyte = (uint32_t)(ks * 16) * 2;
            #pragma unroll
            for (int nt2 = 0; nt2 < 4; nt2++) {
                uint32_t kH[4], kL[4];
                uint32_t addr = sb + (uint32_t)(nt2 * 16 + krow_b) * TSTRB + kbyte + kk_b;
                ldmatrix_x4(kH, addr);
                ldmatrix_x4(kL, addr + AKV);
                float* d0 = sAcc[nt2 * 2];
                float* d1 = sAcc[nt2 * 2 + 1];
                mma_bf16(d0, qHi[ks], &kH[0], d0);
                mma_bf16(d1, qHi[ks], &kH[2], d1);
                mma_bf16(d0, qHi[ks], &kL[0], d0);
                mma_bf16(d1, qHi[ks], &kL[2], d1);
                mma_bf16(d0, qLo[ks], &kH[0], d0);
                mma_bf16(d1, qLo[ks], &kH[2], d1);
            }
        }

        // ---- tail masking (uniform branch; only last partial tile) ----
        if (t == ntiles - 1 && (nkb & 63) != 0) {
            const int lim = nkb - t * 64;   // 1..63
            #pragma unroll
            for (int nt = 0; nt < 8; nt++) {
                int c0 = nt * 8 + mcol;
                if (c0 >= lim)     { sAcc[nt][0] = MASKED; sAcc[nt][2] = MASKED; }
                if (c0 + 1 >= lim) { sAcc[nt][1] = MASKED; sAcc[nt][3] = MASKED; }
            }
        }

        // ---- online softmax (base-2 domain) ----
        float rm0 = -1e30f, rm1 = -1e30f;
        #pragma unroll
        for (int nt = 0; nt < 8; nt++) {
            rm0 = fmaxf(rm0, fmaxf(sAcc[nt][0], sAcc[nt][1]));
            rm1 = fmaxf(rm1, fmaxf(sAcc[nt][2], sAcc[nt][3]));
        }
        rm0 = fmaxf(rm0, __shfl_xor_sync(0xffffffffu, rm0, 1));
        rm0 = fmaxf(rm0, __shfl_xor_sync(0xffffffffu, rm0, 2));
        rm1 = fmaxf(rm1, __shfl_xor_sync(0xffffffffu, rm1, 1));
        rm1 = fmaxf(rm1, __shfl_xor_sync(0xffffffffu, rm1, 2));

        float m0n = fmaxf(m0, rm0), m1n = fmaxf(m1, rm1);
        float a0 = exp2f(m0 - m0n), a1 = exp2f(m1 - m1n);
        float ps0 = 0.f, ps1 = 0.f;
        #pragma unroll
        for (int nt = 0; nt < 8; nt++) {
            float p0 = exp2f(sAcc[nt][0] - m0n);
            float p1 = exp2f(sAcc[nt][1] - m0n);
            float p2 = exp2f(sAcc[nt][2] - m1n);
            float p3 = exp2f(sAcc[nt][3] - m1n);
            sAcc[nt][0] = p0; sAcc[nt][1] = p1; sAcc[nt][2] = p2; sAcc[nt][3] = p3;
            ps0 += p0 + p1; ps1 += p2 + p3;
            oAcc[nt][0] *= a0; oAcc[nt][1] *= a0;
            oAcc[nt][2] *= a1; oAcc[nt][3] *= a1;
        }
        ps0 += __shfl_xor_sync(0xffffffffu, ps0, 1);
        ps0 += __shfl_xor_sync(0xffffffffu, ps0, 2);
        ps1 += __shfl_xor_sync(0xffffffffu, ps1, 1);
        ps1 += __shfl_xor_sync(0xffffffffu, ps1, 2);
        l0 = l0 * a0 + ps0;
        l1 = l1 * a1 + ps1;
        m0 = m0n; m1 = m1n;

        // ---- O += P @ V (3 passes; halves interleaved) ----
        #pragma unroll
        for (int ks = 0; ks < 4; ks++) {
            uint32_t aH[4], aL[4];
            pack_hilo(sAcc[2 * ks][0],     sAcc[2 * ks][1],     aH[0], aL[0]);
            pack_hilo(sAcc[2 * ks][2],     sAcc[2 * ks][3],     aH[1], aL[1]);
            pack_hilo(sAcc[2 * ks + 1][0], sAcc[2 * ks + 1][1], aH[2], aL[2]);
            pack_hilo(sAcc[2 * ks + 1][2], sAcc[2 * ks + 1][3], aH[3], aL[3]);

            #pragma unroll
            for (int nt2 = 0; nt2 < 4; nt2++) {
                uint32_t vH[4], vL[4];
                uint32_t addr = sb + 2 * AKV + (uint32_t)(ks * 16 + vrow_b) * TSTRB
                              + (uint32_t)(nt2 * 16) * 2 + vcol_b;
                ldmatrix_x4_trans(vH, addr);
                ldmatrix_x4_trans(vL, addr + AKV);
                float* d0 = oAcc[nt2 * 2];
                float* d1 = oAcc[nt2 * 2 + 1];
                mma_bf16(d0, aH, &vH[0], d0);
                mma_bf16(d1, aH, &vH[2], d1);
                mma_bf16(d0, aL, &vH[0], d0);
                mma_bf16(d1, aL, &vH[2], d1);
                mma_bf16(d0, aH, &vL[0], d0);
                mma_bf16(d1, aH, &vL[2], d1);
            }
        }
    }

    // ---- epilogue: write split bf16 attention output ----
    float i0 = 1.f / l0, i1 = 1.f / l1;
    const int r  = lane >> 2;
    const int c2 = (lane & 3) * 2;
    const int row0 = q0 + wid * 16 + r;
    #pragma unroll
    for (int nt = 0; nt < 8; nt++) {
        int col = h * DH + nt * 8 + c2;
        uint32_t h01, l01, h23, l23;
        pack_hilo(oAcc[nt][0] * i0, oAcc[nt][1] * i0, h01, l01);
        pack_hilo(oAcc[nt][2] * i1, oAcc[nt][3] * i1, h23, l23);
        *(uint32_t*)(ohi + (size_t)(b * SEQ + row0) * DM + col) = h01;
        *(uint32_t*)(olo + (size_t)(b * SEQ + row0) * DM + col) = l01;
        *(uint32_t*)(ohi + (size_t)(b * SEQ + row0 + 8) * DM + col) = h23;
        *(uint32_t*)(olo + (size_t)(b * SEQ + row0 + 8) * DM + col) = l23;
    }
}

// ---------------------------------------------------------------------------
extern "C" void kernel_launch(void* const* d_in, const int* in_sizes, int n_in,
                              void* d_out, int out_size) {
    const float* query = (const float*)d_in[0];
    const float* key_t = (const float*)d_in[1];
    const float* value = (const float*)d_in[2];
    const int*   mask  = (const int*)  d_in[3];
    const float* Wq = (const float*)d_in[4];
    const float* bq = (const float*)d_in[5];
    const float* Wk = (const float*)d_in[6];
    const float* bk = (const float*)d_in[7];
    const float* Wv = (const float*)d_in[8];
    const float* bv = (const float*)d_in[9];
    const float* Wo = (const float*)d_in[10];
    const float* bo = (const float*)d_in[11];
    float* out = (float*)d_out;

    __nv_bfloat16 *qin_hi, *qin_lo, *kin_hi, *kin_lo, *vin_hi, *vin_lo;
    __nv_bfloat16 *wq_hi, *wq_lo, *wk_hi, *wk_lo, *wv_hi, *wv_lo, *wo_hi, *wo_lo;
    __nv_bfloat16 *Q_hi, *Q_lo, *K_hi, *K_lo, *V_hi, *V_lo, *at_hi, *at_lo;
    __nv_bfloat16 *Kc_hi, *Kc_lo, *Vc_hi, *Vc_lo;
    int *idxp, *nkp;
    cudaGetSymbolAddress((void**)&qin_hi, g_qin_hi);
    cudaGetSymbolAddress((void**)&qin_lo, g_qin_lo);
    cudaGetSymbolAddress((void**)&kin_hi, g_kin_hi);
    cudaGetSymbolAddress((void**)&kin_lo, g_kin_lo);
    cudaGetSymbolAddress((void**)&vin_hi, g_vin_hi);
    cudaGetSymbolAddress((void**)&vin_lo, g_vin_lo);
    cudaGetSymbolAddress((void**)&wq_hi, g_wq_hi);
    cudaGetSymbolAddress((void**)&wq_lo, g_wq_lo);
    cudaGetSymbolAddress((void**)&wk_hi, g_wk_hi);
    cudaGetSymbolAddress((void**)&wk_lo, g_wk_lo);
    cudaGetSymbolAddress((void**)&wv_hi, g_wv_hi);
    cudaGetSymbolAddress((void**)&wv_lo, g_wv_lo);
    cudaGetSymbolAddress((void**)&wo_hi, g_wo_hi);
    cudaGetSymbolAddress((void**)&wo_lo, g_wo_lo);
    cudaGetSymbolAddress((void**)&Q_hi, g_Q_hi);
    cudaGetSymbolAddress((void**)&Q_lo, g_Q_lo);
    cudaGetSymbolAddress((void**)&K_hi, g_K_hi);
    cudaGetSymbolAddress((void**)&K_lo, g_K_lo);
    cudaGetSymbolAddress((void**)&V_hi, g_V_hi);
    cudaGetSymbolAddress((void**)&V_lo, g_V_lo);
    cudaGetSymbolAddress((void**)&at_hi, g_at_hi);
    cudaGetSymbolAddress((void**)&at_lo, g_at_lo);
    cudaGetSymbolAddress((void**)&Kc_hi, g_Kc_hi);
    cudaGetSymbolAddress((void**)&Kc_lo, g_Kc_lo);
    cudaGetSymbolAddress((void**)&Vc_hi, g_Vc_hi);
    cudaGetSymbolAddress((void**)&Vc_lo, g_Vc_lo);
    cudaGetSymbolAddress((void**)&idxp, g_idx);
    cudaGetSymbolAddress((void**)&nkp, g_nk);

    const int M = BATCH * SEQ;       // 4096
    const int n4m = MELEMS / 4;
    const int n4w = WELEMS / 4;

    cudaFuncSetAttribute(gemm_qkv_kernel,
                         cudaFuncAttributeMaxDynamicSharedMemorySize, GEMM_PS_SMEM);
    cudaFuncSetAttribute(gemm_out_kernel,
                         cudaFuncAttributeMaxDynamicSharedMemorySize, GEMM_PS_SMEM);
    cudaFuncSetAttribute(attn_ps_kernel,
                         cudaFuncAttributeMaxDynamicSharedMemorySize, ATT_SMEM);

    // Pre-pass splits (region-batched) + mask index scan
    dim3 s3grid((n4m + 255) / 256, 3);
    split3_kernel<<<s3grid, 256>>>((const float4*)query, (const float4*)key_t,
                                   (const float4*)value,
                                   (uint2*)qin_hi, (uint2*)qin_lo,
                                   (uint2*)kin_hi, (uint2*)kin_lo,
                                   (uint2*)vin_hi, (uint2*)vin_lo, n4m);
    dim3 s4grid((n4w + 255) / 256, 4);
    split4_kernel<<<s4grid, 256>>>((const float4*)Wq, (const float4*)Wk,
                                   (const float4*)Wv, (const float4*)Wo,
                                   (uint2*)wq_hi, (uint2*)wq_lo,
                                   (uint2*)wk_hi, (uint2*)wk_lo,
                                   (uint2*)wv_hi, (uint2*)wv_lo,
                                   (uint2*)wo_hi, (uint2*)wo_lo, n4w);
    mask_compact_idx<<<BATCH, 32>>>(mask, idxp, nkp);

    // Fused QKV projections: 3 regions x 16 n-blocks = 48
    dim3 qkvgrid(48, M / 128);
    gemm_qkv_kernel<<<qkvgrid, 256, GEMM_PS_SMEM>>>(
        qin_hi, qin_lo, kin_hi, kin_lo, vin_hi, vin_lo,
        wq_hi, wq_lo, wk_hi, wk_lo, wv_hi, wv_lo,
        bq, bk, bv, Q_hi, Q_lo, K_hi, K_lo, V_hi, V_lo);

    // Compact K/V rows to unmasked keys
    dim3 ggrid2(SEQ, BATCH);
    gather_kv<<<ggrid2, 128>>>((const uint4*)K_hi, (const uint4*)K_lo,
                               (const uint4*)V_hi, (const uint4*)V_lo,
                               (uint4*)Kc_hi, (uint4*)Kc_lo,
                               (uint4*)Vc_hi, (uint4*)Vc_lo, idxp, nkp);

    dim3 agrid(SEQ / 64, NH, BATCH); // (32, 16, 2)
    attn_ps_kernel<<<agrid, 128, ATT_SMEM>>>(Q_hi, Q_lo, Kc_hi, Kc_lo, Vc_hi, Vc_lo,
                                             nkp, at_hi, at_lo);

    dim3 ogrid(DM / 64, M / 128);    // (16, 32)
    gemm_out_kernel<<<ogrid, 256, GEMM_PS_SMEM>>>(at_hi, at_lo, wo_hi, wo_lo, bo, out);
}